// round 3
// baseline (speedup 1.0000x reference)
#include <cuda_runtime.h>
#include <math_constants.h>

#define RES     8
#define FEAT    512           // RES^3
#define NCLS    40
#define BMAX    64

// ---------------- device scratch (no allocs allowed) ----------------
__device__ float g_min[BMAX * 3];
__device__ float g_max[BMAX * 3];
__device__ int   g_hist[BMAX * FEAT];

// ---------------- float atomic min/max via int trick ----------------
__device__ __forceinline__ void atomicMinF(float* addr, float val) {
    if (__float_as_int(val) >= 0)
        atomicMin((int*)addr, __float_as_int(val));
    else
        atomicMax((unsigned int*)addr, __float_as_uint(val));
}
__device__ __forceinline__ void atomicMaxF(float* addr, float val) {
    if (__float_as_int(val) >= 0)
        atomicMax((int*)addr, __float_as_int(val));
    else
        atomicMin((unsigned int*)addr, __float_as_uint(val));
}

// ---------------- kernel 0: init scratch ----------------
__global__ void init_kernel(int B) {
    int i = blockIdx.x * blockDim.x + threadIdx.x;
    if (i < B * FEAT) g_hist[i] = 0;
    if (i < B * 3) {
        g_min[i] = __int_as_float(0x7f800000);   // +inf
        g_max[i] = __int_as_float(0xff800000);   // -inf
    }
}

// ---------------- kernel 1: per-batch min/max ----------------
// Each "group" = 4 points = 12 floats = 3 float4 loads.
__global__ __launch_bounds__(256) void minmax_kernel(
    const float* __restrict__ x, int N, int blocksPerBatch)
{
    int b  = blockIdx.x / blocksPerBatch;
    int bb = blockIdx.x % blocksPerBatch;
    const float4* base = (const float4*)(x + (size_t)b * N * 3);

    float mn0 =  CUDART_INF_F, mn1 =  CUDART_INF_F, mn2 =  CUDART_INF_F;
    float mx0 = -CUDART_INF_F, mx1 = -CUDART_INF_F, mx2 = -CUDART_INF_F;

    int ngroups = N >> 2;
    int stride  = blocksPerBatch * blockDim.x;
    for (int g = bb * blockDim.x + threadIdx.x; g < ngroups; g += stride) {
        float4 a = base[3 * g + 0];
        float4 v = base[3 * g + 1];
        float4 c = base[3 * g + 2];
        // p0=(a.x,a.y,a.z) p1=(a.w,v.x,v.y) p2=(v.z,v.w,c.x) p3=(c.y,c.z,c.w)
        mn0 = fminf(mn0, fminf(fminf(a.x, a.w), fminf(v.z, c.y)));
        mx0 = fmaxf(mx0, fmaxf(fmaxf(a.x, a.w), fmaxf(v.z, c.y)));
        mn1 = fminf(mn1, fminf(fminf(a.y, v.x), fminf(v.w, c.z)));
        mx1 = fmaxf(mx1, fmaxf(fmaxf(a.y, v.x), fmaxf(v.w, c.z)));
        mn2 = fminf(mn2, fminf(fminf(a.z, v.y), fminf(c.x, c.w)));
        mx2 = fmaxf(mx2, fmaxf(fmaxf(a.z, v.y), fmaxf(c.x, c.w)));
    }
    // tail points (N % 4)
    int tail = N & 3;
    if (bb == 0 && threadIdx.x < tail) {
        int n = (ngroups << 2) + threadIdx.x;
        const float* p = x + ((size_t)b * N + n) * 3;
        mn0 = fminf(mn0, p[0]); mx0 = fmaxf(mx0, p[0]);
        mn1 = fminf(mn1, p[1]); mx1 = fmaxf(mx1, p[1]);
        mn2 = fminf(mn2, p[2]); mx2 = fmaxf(mx2, p[2]);
    }

    // warp reduce
    #pragma unroll
    for (int off = 16; off > 0; off >>= 1) {
        mn0 = fminf(mn0, __shfl_xor_sync(0xffffffffu, mn0, off));
        mn1 = fminf(mn1, __shfl_xor_sync(0xffffffffu, mn1, off));
        mn2 = fminf(mn2, __shfl_xor_sync(0xffffffffu, mn2, off));
        mx0 = fmaxf(mx0, __shfl_xor_sync(0xffffffffu, mx0, off));
        mx1 = fmaxf(mx1, __shfl_xor_sync(0xffffffffu, mx1, off));
        mx2 = fmaxf(mx2, __shfl_xor_sync(0xffffffffu, mx2, off));
    }

    __shared__ float red[8][6];
    int warp = threadIdx.x >> 5, lane = threadIdx.x & 31;
    if (lane == 0) {
        red[warp][0] = mn0; red[warp][1] = mn1; red[warp][2] = mn2;
        red[warp][3] = mx0; red[warp][4] = mx1; red[warp][5] = mx2;
    }
    __syncthreads();
    if (warp == 0 && lane < 6) {
        int nw = blockDim.x >> 5;
        float v = red[0][lane];
        for (int w = 1; w < nw; w++) {
            float o = red[w][lane];
            v = (lane < 3) ? fminf(v, o) : fmaxf(v, o);
        }
        if (lane < 3) atomicMinF(&g_min[b * 3 + lane], v);
        else          atomicMaxF(&g_max[b * 3 + (lane - 3)], v);
    }
}

// ---------------- kernel 2: histogram ----------------
__device__ __forceinline__ int bin_of(float p, float mn, float sc) {
    int i = (int)floorf((p - mn) * sc);
    return min(max(i, 0), RES - 1);
}

__global__ __launch_bounds__(256) void hist_kernel(
    const float* __restrict__ x, int N, int blocksPerBatch)
{
    __shared__ int sh[FEAT];
    int b  = blockIdx.x / blocksPerBatch;
    int bb = blockIdx.x % blocksPerBatch;

    for (int i = threadIdx.x; i < FEAT; i += blockDim.x) sh[i] = 0;

    float mn0 = g_min[b * 3 + 0], mn1 = g_min[b * 3 + 1], mn2 = g_min[b * 3 + 2];
    float r0 = g_max[b * 3 + 0] - mn0;
    float r1 = g_max[b * 3 + 1] - mn1;
    float r2 = g_max[b * 3 + 2] - mn2;
    float sc0 = (float)RES / (r0 > 0.f ? r0 : 1.0f);
    float sc1 = (float)RES / (r1 > 0.f ? r1 : 1.0f);
    float sc2 = (float)RES / (r2 > 0.f ? r2 : 1.0f);
    __syncthreads();

    const float4* base = (const float4*)(x + (size_t)b * N * 3);
    int ngroups = N >> 2;
    int stride  = blocksPerBatch * blockDim.x;
    for (int g = bb * blockDim.x + threadIdx.x; g < ngroups; g += stride) {
        float4 a = base[3 * g + 0];
        float4 v = base[3 * g + 1];
        float4 c = base[3 * g + 2];
        // p0=(a.x,a.y,a.z) p1=(a.w,v.x,v.y) p2=(v.z,v.w,c.x) p3=(c.y,c.z,c.w)
        int b0 = (bin_of(a.x, mn0, sc0) * RES + bin_of(a.y, mn1, sc1)) * RES + bin_of(a.z, mn2, sc2);
        int b1 = (bin_of(a.w, mn0, sc0) * RES + bin_of(v.x, mn1, sc1)) * RES + bin_of(v.y, mn2, sc2);
        int b2 = (bin_of(v.z, mn0, sc0) * RES + bin_of(v.w, mn1, sc1)) * RES + bin_of(c.x, mn2, sc2);
        int b3 = (bin_of(c.y, mn0, sc0) * RES + bin_of(c.z, mn1, sc1)) * RES + bin_of(c.w, mn2, sc2);
        atomicAdd(&sh[b0], 1);
        atomicAdd(&sh[b1], 1);
        atomicAdd(&sh[b2], 1);
        atomicAdd(&sh[b3], 1);
    }
    int tail = N & 3;
    if (bb == 0 && threadIdx.x < tail) {
        int n = (ngroups << 2) + threadIdx.x;
        const float* p = x + ((size_t)b * N + n) * 3;
        int bn = (bin_of(p[0], mn0, sc0) * RES + bin_of(p[1], mn1, sc1)) * RES + bin_of(p[2], mn2, sc2);
        atomicAdd(&sh[bn], 1);
    }
    __syncthreads();
    for (int i = threadIdx.x; i < FEAT; i += blockDim.x) {
        int v = sh[i];
        if (v) atomicAdd(&g_hist[b * FEAT + i], v);
    }
}

// ---------------- kernel 3: linear layer — one warp per output ----------------
// 64 batches x 40 classes = 2560 warps. Each warp: dot(hist[b][:], W[c][:]) over
// 512 elems via 4x LDG.128 per operand per lane -> 16 independent FMAs -> shfl reduce.
__global__ __launch_bounds__(256) void linear_kernel(
    const float* __restrict__ W, const float* __restrict__ bias,
    float* __restrict__ out, int N, int B)
{
    int wid  = (blockIdx.x * blockDim.x + threadIdx.x) >> 5;
    int lane = threadIdx.x & 31;
    if (wid >= B * NCLS) return;
    int b = wid / NCLS;
    int c = wid - b * NCLS;

    const float4* wr = (const float4*)(W + (size_t)c * FEAT);
    const int4*   hr = (const int4*)(g_hist + b * FEAT);

    float s = 0.f;
    #pragma unroll
    for (int i = 0; i < FEAT / 4 / 32; i++) {     // 4 iterations
        int idx = lane + 32 * i;
        float4 w4 = wr[idx];
        int4   h4 = hr[idx];
        s += w4.x * (float)h4.x;
        s += w4.y * (float)h4.y;
        s += w4.z * (float)h4.z;
        s += w4.w * (float)h4.w;
    }
    #pragma unroll
    for (int off = 16; off > 0; off >>= 1)
        s += __shfl_xor_sync(0xffffffffu, s, off);
    if (lane == 0)
        out[wid] = s * (1.0f / (float)N) + bias[c];
}

// ---------------- launch ----------------
extern "C" void kernel_launch(void* const* d_in, const int* in_sizes, int n_in,
                              void* d_out, int out_size)
{
    const float* x    = (const float*)d_in[0];
    const float* W    = (const float*)d_in[1];
    const float* bias = (const float*)d_in[2];
    float* out = (float*)d_out;

    int B = out_size / NCLS;              // 64
    if (B > BMAX) B = BMAX;
    int N = in_sizes[0] / (3 * B);        // 100000

    int initThreads = B * FEAT;           // covers B*3 too
    init_kernel<<<(initThreads + 255) / 256, 256>>>(B);

    const int bpbMM = 8;
    minmax_kernel<<<B * bpbMM, 256>>>(x, N, bpbMM);

    const int bpbH = 16;
    hist_kernel<<<B * bpbH, 256>>>(x, N, bpbH);

    int nWarps = B * NCLS;                // 2560
    int nBlocks = (nWarps * 32 + 255) / 256;
    linear_kernel<<<nBlocks, 256>>>(W, bias, out, N, B);
}

// round 4
// speedup vs baseline: 1.3140x; 1.3140x over previous
#include <cuda_runtime.h>
#include <math_constants.h>

#define RES      8
#define FEAT     512          // RES^3
#define NCLS     40
#define BMAX     64
#define BPB      8            // blocks per batch
#define NTHREADS 256

// ---------------- device scratch (no allocs allowed) ----------------
__device__ float g_mmP[BMAX * BPB * 6];    // per-block minmax partials
__device__ int   g_hist[BMAX * FEAT];
__device__ unsigned          g_barCount = 0;
__device__ volatile unsigned g_barGen   = 0;

// ---------------- software grid barrier (self-resetting, replay-safe) ----
__device__ __forceinline__ void gridBarrier(int nblocks) {
    __syncthreads();
    if (threadIdx.x == 0) {
        unsigned gen = g_barGen;
        __threadfence();                       // make my stores visible
        unsigned t = atomicAdd(&g_barCount, 1u);
        if (t == (unsigned)nblocks - 1u) {
            g_barCount = 0;                    // reset for next barrier/replay
            __threadfence();
            g_barGen = gen + 1u;               // release
        } else {
            while (g_barGen == gen) { __nanosleep(32); }
            __threadfence();                   // acquire
        }
    }
    __syncthreads();
}

__device__ __forceinline__ int bin_of(float p, float mn, float sc) {
    int i = (int)floorf((p - mn) * sc);
    return min(max(i, 0), RES - 1);
}

// ---------------- fused kernel ----------------
__global__ __launch_bounds__(NTHREADS, 4) void fused_kernel(
    const float* __restrict__ x, const float* __restrict__ W,
    const float* __restrict__ bias, float* __restrict__ out,
    int N, int B, int nblocks)
{
    __shared__ float red[8][6];
    __shared__ float s_mm[6];
    __shared__ int   sh[FEAT];

    const int b  = blockIdx.x / BPB;
    const int bb = blockIdx.x % BPB;
    const int tid  = threadIdx.x;
    const int warp = tid >> 5, lane = tid & 31;

    const float4* base = (const float4*)(x + (size_t)b * N * 3);
    const int ngroups = N >> 2;
    const int per = (ngroups + BPB - 1) / BPB;
    const int g0 = bb * per;
    const int g1 = min(g0 + per, ngroups);

    // ===================== Phase A: min/max (+ zero hist, warm W) =====================
    float mn0 =  CUDART_INF_F, mn1 =  CUDART_INF_F, mn2 =  CUDART_INF_F;
    float mx0 = -CUDART_INF_F, mx1 = -CUDART_INF_F, mx2 = -CUDART_INF_F;

    for (int g = g0 + tid; g < g1; g += NTHREADS) {
        float4 a = base[3 * g + 0];
        float4 v = base[3 * g + 1];
        float4 c = base[3 * g + 2];
        // p0=(a.x,a.y,a.z) p1=(a.w,v.x,v.y) p2=(v.z,v.w,c.x) p3=(c.y,c.z,c.w)
        mn0 = fminf(mn0, fminf(fminf(a.x, a.w), fminf(v.z, c.y)));
        mx0 = fmaxf(mx0, fmaxf(fmaxf(a.x, a.w), fmaxf(v.z, c.y)));
        mn1 = fminf(mn1, fminf(fminf(a.y, v.x), fminf(v.w, c.z)));
        mx1 = fmaxf(mx1, fmaxf(fmaxf(a.y, v.x), fmaxf(v.w, c.z)));
        mn2 = fminf(mn2, fminf(fminf(a.z, v.y), fminf(c.x, c.w)));
        mx2 = fmaxf(mx2, fmaxf(fmaxf(a.z, v.y), fmaxf(c.x, c.w)));
    }
    // tail points (N % 4) handled by block bb==0
    int tail = N & 3;
    if (bb == 0 && tid < tail) {
        int n = (ngroups << 2) + tid;
        const float* p = x + ((size_t)b * N + n) * 3;
        mn0 = fminf(mn0, p[0]); mx0 = fmaxf(mx0, p[0]);
        mn1 = fminf(mn1, p[1]); mx1 = fmaxf(mx1, p[1]);
        mn2 = fminf(mn2, p[2]); mx2 = fmaxf(mx2, p[2]);
    }

    // zero this batch's hist row (bb==0 blocks) — before barrier
    if (bb == 0)
        for (int i = tid; i < FEAT; i += NTHREADS) g_hist[b * FEAT + i] = 0;

    // warm W into L2 for phase C: 512 blocks x 10 float4 = 20480 floats = all of W
    if (tid < 10) {
        int wi = blockIdx.x * 10 + tid;
        if (wi < NCLS * FEAT / 4) {
            float4 w4 = ((const float4*)W)[wi];
            asm volatile("" :: "f"(w4.x), "f"(w4.y), "f"(w4.z), "f"(w4.w));
        }
    }

    // block-reduce min/max
    #pragma unroll
    for (int off = 16; off > 0; off >>= 1) {
        mn0 = fminf(mn0, __shfl_xor_sync(0xffffffffu, mn0, off));
        mn1 = fminf(mn1, __shfl_xor_sync(0xffffffffu, mn1, off));
        mn2 = fminf(mn2, __shfl_xor_sync(0xffffffffu, mn2, off));
        mx0 = fmaxf(mx0, __shfl_xor_sync(0xffffffffu, mx0, off));
        mx1 = fmaxf(mx1, __shfl_xor_sync(0xffffffffu, mx1, off));
        mx2 = fmaxf(mx2, __shfl_xor_sync(0xffffffffu, mx2, off));
    }
    if (lane == 0) {
        red[warp][0] = mn0; red[warp][1] = mn1; red[warp][2] = mn2;
        red[warp][3] = mx0; red[warp][4] = mx1; red[warp][5] = mx2;
    }
    __syncthreads();
    if (warp == 0 && lane < 6) {
        float v = red[0][lane];
        #pragma unroll
        for (int w = 1; w < NTHREADS / 32; w++) {
            float o = red[w][lane];
            v = (lane < 3) ? fminf(v, o) : fmaxf(v, o);
        }
        g_mmP[blockIdx.x * 6 + lane] = v;      // plain store, no init needed
    }

    gridBarrier(nblocks);

    // ===================== Phase B: histogram =====================
    if (tid < 6) {
        float v = g_mmP[(b * BPB) * 6 + tid];
        #pragma unroll
        for (int p = 1; p < BPB; p++) {
            float o = g_mmP[(b * BPB + p) * 6 + tid];
            v = (tid < 3) ? fminf(v, o) : fmaxf(v, o);
        }
        s_mm[tid] = v;
    }
    for (int i = tid; i < FEAT; i += NTHREADS) sh[i] = 0;
    __syncthreads();

    const float mnx = s_mm[0], mny = s_mm[1], mnz = s_mm[2];
    float r0 = s_mm[3] - mnx, r1 = s_mm[4] - mny, r2 = s_mm[5] - mnz;
    const float sc0 = (float)RES / (r0 > 0.f ? r0 : 1.0f);
    const float sc1 = (float)RES / (r1 > 0.f ? r1 : 1.0f);
    const float sc2 = (float)RES / (r2 > 0.f ? r2 : 1.0f);

    for (int g = g0 + tid; g < g1; g += NTHREADS) {
        float4 a = base[3 * g + 0];
        float4 v = base[3 * g + 1];
        float4 c = base[3 * g + 2];
        int b0 = (bin_of(a.x, mnx, sc0) * RES + bin_of(a.y, mny, sc1)) * RES + bin_of(a.z, mnz, sc2);
        int b1 = (bin_of(a.w, mnx, sc0) * RES + bin_of(v.x, mny, sc1)) * RES + bin_of(v.y, mnz, sc2);
        int b2 = (bin_of(v.z, mnx, sc0) * RES + bin_of(v.w, mny, sc1)) * RES + bin_of(c.x, mnz, sc2);
        int b3 = (bin_of(c.y, mnx, sc0) * RES + bin_of(c.z, mny, sc1)) * RES + bin_of(c.w, mnz, sc2);
        atomicAdd(&sh[b0], 1);
        atomicAdd(&sh[b1], 1);
        atomicAdd(&sh[b2], 1);
        atomicAdd(&sh[b3], 1);
    }
    if (bb == 0 && tid < tail) {
        int n = (ngroups << 2) + tid;
        const float* p = x + ((size_t)b * N + n) * 3;
        int bn = (bin_of(p[0], mnx, sc0) * RES + bin_of(p[1], mny, sc1)) * RES + bin_of(p[2], mnz, sc2);
        atomicAdd(&sh[bn], 1);
    }
    __syncthreads();
    for (int i = tid; i < FEAT; i += NTHREADS) {
        int v = sh[i];
        if (v) atomicAdd(&g_hist[b * FEAT + i], v);
    }

    gridBarrier(nblocks);

    // ===================== Phase C: linear, warp per (batch, class) =====================
    int wid = blockIdx.x * (NTHREADS / 32) + warp;   // 512*8 = 4096 warps, need B*NCLS
    if (wid < B * NCLS) {
        int ob = wid / NCLS;
        int c  = wid - ob * NCLS;
        const float4* wr = (const float4*)(W + (size_t)c * FEAT);
        const int4*   hr = (const int4*)(g_hist + ob * FEAT);
        float s = 0.f;
        #pragma unroll
        for (int i = 0; i < FEAT / 4 / 32; i++) {    // 4 iterations
            int idx = lane + 32 * i;
            float4 w4 = wr[idx];
            int4   h4 = hr[idx];
            s += w4.x * (float)h4.x;
            s += w4.y * (float)h4.y;
            s += w4.z * (float)h4.z;
            s += w4.w * (float)h4.w;
        }
        #pragma unroll
        for (int off = 16; off > 0; off >>= 1)
            s += __shfl_xor_sync(0xffffffffu, s, off);
        if (lane == 0)
            out[wid] = s * (1.0f / (float)N) + bias[c];
    }
}

// ---------------- launch ----------------
extern "C" void kernel_launch(void* const* d_in, const int* in_sizes, int n_in,
                              void* d_out, int out_size)
{
    const float* x    = (const float*)d_in[0];
    const float* W    = (const float*)d_in[1];
    const float* bias = (const float*)d_in[2];
    float* out = (float*)d_out;

    int B = out_size / NCLS;              // 64
    if (B > BMAX) B = BMAX;
    int N = in_sizes[0] / (3 * B);        // 100000

    int nblocks = B * BPB;                // 512 — all resident (<= 148*4 guaranteed by launch_bounds)
    fused_kernel<<<nblocks, NTHREADS>>>(x, W, bias, out, N, B, nblocks);
}